// round 10
// baseline (speedup 1.0000x reference)
#include <cuda_runtime.h>
#include <cuda_fp16.h>
#include <mma.h>
#include <cstdint>

using namespace nvcuda;

// Problem constants
#define BSZ   32
#define TN    512
#define DN    256
#define FN    256
#define ROWS  (BSZ * TN)        // 16384
#define KSUM  768               // 3 * 256
#define MEL   2048
#define GROWS (BSZ * MEL)       // 65536 gather rows
#define OUT_LR_ELEMS (BSZ * MEL * DN)   // 16777216

// GEMM tiling (fp16 m16n16k16), BM=64 x BN=256, warp tile 32x64,
// BK=64 halves, 2-stage cp.async, 2 CTAs/SM.
#define BM       64
#define BKH      64
#define LDA      72              // padded leading dim in halves (144B rows)
#define NCHUNK   12              // 768 / 64
#define NSTAGE   2
#define NTHREADS 256
#define STAGE_LD 264             // fp32 epilogue stage leading dim

// ---------------- device scratch ----------------
__device__ __half g_xh[ROWS * DN];      // x in fp16 (RN)
__device__ __half g_h1h[ROWS * FN];     // conv1 out (LN+relu), fp16 (RN)
__device__ __half g_w1h[KSUM * FN];     // w transposed [f][kk], kk=k*256+d
__device__ __half g_w2h[KSUM * FN];
__device__ int    g_map[GROWS];

// ---------------- smem layout (bytes) ----------------
// per stage: A = 64 x 144B = 9216 ; B = 256 x 144B = 36864 ; stride 46080
// 2 stages = 92160. fp32 epilogue stage (64 x 264 x 4 = 67584) UNIONs at 0.
#define STG_STRIDE   46080
#define OFF_B_IN_STG 9216
#define OFF_STAGE    0
#define OFF_BIAS     92160
#define OFF_GAMMA    (OFF_BIAS  + 1024)
#define OFF_BETA     (OFF_GAMMA + 1024)
#define OFF_LW       (OFF_BETA  + 1024)
#define SMEM_BYTES   (OFF_LW + 1024)    // 96256  -> 2 CTAs/SM

__device__ __forceinline__ float warp_sum(float v) {
    v += __shfl_xor_sync(0xffffffffu, v, 16);
    v += __shfl_xor_sync(0xffffffffu, v, 8);
    v += __shfl_xor_sync(0xffffffffu, v, 4);
    v += __shfl_xor_sync(0xffffffffu, v, 2);
    v += __shfl_xor_sync(0xffffffffu, v, 1);
    return v;
}

__device__ __forceinline__ void cp16(uint32_t dst, const void* src, int szbytes) {
    asm volatile("cp.async.ca.shared.global [%0], [%1], 16, %2;"
                 :: "r"(dst), "l"(src), "r"(szbytes));
}

// ============================================================
// Fused prep kernel (512 threads/block):
//   blocks [0, 384)    : convert weights (transpose + fp16)
//   blocks [384, 896)  : convert x to fp16, 4 float4/thread (MLP=4)
//   blocks [896, 928)  : per-batch duration scan -> frame map
// ============================================================
#define PREP_WB   384
#define PREP_XB   512
#define PREP_GRID (PREP_WB + PREP_XB + BSZ)

__global__ void __launch_bounds__(512)
prep_kernel(const float* __restrict__ w1, const float* __restrict__ w2,
            const float* __restrict__ x,  const int* __restrict__ target) {
    const int blk = blockIdx.x;
    if (blk < PREP_WB) {
        int i = blk * 512 + threadIdx.x;          // i < KSUM*FN
        int f  = i / KSUM;
        int kk = i - f * KSUM;
        int k  = kk >> 8;
        int d  = kk & 255;
        int src = f * KSUM + d * 3 + k;           // w[f][d][k]
        g_w1h[i] = __float2half_rn(w1[src]);
        g_w2h[i] = __float2half_rn(w2[src]);
    } else if (blk < PREP_WB + PREP_XB) {
        const int base = (blk - PREP_WB) * 2048 + threadIdx.x;  // float4 units
        float4 v[4];
#pragma unroll
        for (int k = 0; k < 4; k++)
            v[k] = ((const float4*)x)[base + k * 512];
#pragma unroll
        for (int k = 0; k < 4; k++) {
            __half2 lo = __floats2half2_rn(v[k].x, v[k].y);
            __half2 hi = __floats2half2_rn(v[k].z, v[k].w);
            uint2 pk;
            pk.x = *(uint32_t*)&lo;
            pk.y = *(uint32_t*)&hi;
            ((uint2*)g_xh)[base + k * 512] = pk;
        }
    } else {
        __shared__ int s[TN];
        const int b = blk - PREP_WB - PREP_XB;
        const int t = threadIdx.x;                 // 512 == TN
        const int dur = target[b * TN + t];
        s[t] = dur;
        __syncthreads();
        for (int off = 1; off < TN; off <<= 1) {
            int v = s[t];
            int u = (t >= off) ? s[t - off] : 0;
            __syncthreads();
            s[t] = v + u;
            __syncthreads();
        }
        const int end_   = s[t];
        const int start_ = end_ - dur;
        for (int m = t; m < MEL; m += TN) g_map[b * MEL + m] = -1;
        __syncthreads();
        if (start_ < MEL) {
            int e = end_ < MEL ? end_ : MEL;
            for (int m = start_; m < e; m++) g_map[b * MEL + m] = t;
        }
    }
}

// ============================================================
// LR gather, MLP=8 (exact fp32 copy; output 0 bit-exact)
// ============================================================
__global__ void __launch_bounds__(256)
gather_kernel(const float* __restrict__ x, float* __restrict__ out) {
    const int wid  = threadIdx.x >> 5;
    const int lane = threadIdx.x & 31;
    const int rowBase = blockIdx.x * 32 + wid * 4;   // 4 rows per warp
    const int b = rowBase >> 11;                     // / MEL

    int t[4];
#pragma unroll
    for (int r = 0; r < 4; r++) t[r] = g_map[rowBase + r];

    float4 v[8];
#pragma unroll
    for (int r = 0; r < 4; r++) {
        if (t[r] >= 0) {
            const float4* src = (const float4*)(x + (size_t)(b * TN + t[r]) * DN);
            v[r * 2]     = src[lane];
            v[r * 2 + 1] = src[lane + 32];
        } else {
            v[r * 2]     = make_float4(0.f, 0.f, 0.f, 0.f);
            v[r * 2 + 1] = make_float4(0.f, 0.f, 0.f, 0.f);
        }
    }
#pragma unroll
    for (int r = 0; r < 4; r++) {
        float4* dst = (float4*)(out + (size_t)(rowBase + r) * DN);
        dst[lane]      = v[r * 2];
        dst[lane + 32] = v[r * 2 + 1];
    }
}

// ============================================================
// fp16 wmma conv GEMM: BM=64 x 256, 8 warps (2x4), warp tile 32x64,
// 2-stage cp.async, 2 CTAs/SM. Same pipeline ordering as the proven R6 core.
// ============================================================
template <bool FINAL>
__global__ void __launch_bounds__(NTHREADS, 2)
conv_wmma_kernel(const __half* __restrict__ in,
                 const __half* __restrict__ wh,
                 const float* __restrict__ bias,
                 const float* __restrict__ gamma,
                 const float* __restrict__ beta,
                 const float* __restrict__ lw,
                 const float* __restrict__ lb,
                 __half* __restrict__ outh,
                 float* __restrict__ outf) {
    extern __shared__ char smem[];
    const uint32_t sbase = (uint32_t)__cvta_generic_to_shared(smem);
    const int tid  = threadIdx.x;
    const int wid  = tid >> 5;
    const int lane = tid & 31;
    const int wm   = wid & 1;          // warp row group -> 32 rows
    const int wn   = wid >> 1;         // warp col group -> 64 cols
    const int rowBase = blockIdx.x * BM;

    // stage params
    ((float*)(smem + OFF_BIAS))[tid]  = bias[tid];
    ((float*)(smem + OFF_GAMMA))[tid] = gamma[tid];
    ((float*)(smem + OFF_BETA))[tid]  = beta[tid];
    if (FINAL) ((float*)(smem + OFF_LW))[tid] = lw[tid];

    wmma::fragment<wmma::accumulator, 16, 16, 16, float> acc[2][4];
#pragma unroll
    for (int mt = 0; mt < 2; mt++)
#pragma unroll
        for (int nt = 0; nt < 4; nt++) wmma::fill_fragment(acc[mt][nt], 0.f);

    auto load_tiles = [&](int c) {
        const int slot = c & 1;
        const uint32_t As = sbase + slot * STG_STRIDE;
        const uint32_t Bs = As + OFF_B_IN_STG;
        const int k   = c >> 2;
        const int d0  = (c & 3) << 6;
        const int km1 = k - 1;
#pragma unroll
        for (int i = 0; i < 2; i++) {      // A: 512 16B units
            const int u   = i * NTHREADS + tid;
            const int row = u >> 3, seg = u & 7;
            const int gr  = rowBase + row;
            const int tpos = (gr & (TN - 1)) + km1;
            const bool p = (tpos >= 0 && tpos < TN);
            const __half* src = p ? (in + (size_t)(gr + km1) * DN + d0 + seg * 8) : in;
            cp16(As + row * (LDA * 2) + seg * 16, src, p ? 16 : 0);
        }
#pragma unroll
        for (int i = 0; i < 8; i++) {      // B: 2048 16B units
            const int u = i * NTHREADS + tid;
            const int f = u >> 3, seg = u & 7;
            cp16(Bs + f * (LDA * 2) + seg * 16,
                 wh + (size_t)f * KSUM + c * BKH + seg * 8, 16);
        }
        asm volatile("cp.async.commit_group;" ::: "memory");
    };

    load_tiles(0);

    for (int c = 0; c < NCHUNK; c++) {
        asm volatile("cp.async.wait_group 0;" ::: "memory");
        __syncthreads();
        if (c + 1 < NCHUNK) load_tiles(c + 1);   // fills slot (c+1)&1; safe: its
                                                 // previous contents (chunk c-1)
                                                 // were consumed before the barrier
        const int slot = c & 1;
        const __half* As = (const __half*)(smem + slot * STG_STRIDE);
        const __half* Bs = (const __half*)(smem + slot * STG_STRIDE + OFF_B_IN_STG);
#pragma unroll
        for (int ks = 0; ks < 4; ks++) {
            wmma::fragment<wmma::matrix_a, 16, 16, 16, __half, wmma::row_major> af[2];
            wmma::fragment<wmma::matrix_b, 16, 16, 16, __half, wmma::col_major> bf[4];
#pragma unroll
            for (int mt = 0; mt < 2; mt++)
                wmma::load_matrix_sync(af[mt], As + (wm * 32 + mt * 16) * LDA + ks * 16, LDA);
#pragma unroll
            for (int nt = 0; nt < 4; nt++)
                wmma::load_matrix_sync(bf[nt], Bs + (wn * 64 + nt * 16) * LDA + ks * 16, LDA);
#pragma unroll
            for (int mt = 0; mt < 2; mt++)
#pragma unroll
                for (int nt = 0; nt < 4; nt++)
                    wmma::mma_sync(acc[mt][nt], af[mt], bf[nt], acc[mt][nt]);
        }
        __syncthreads();
    }

    // ---- stage accumulators to smem (union over tiles) ----
    float* stage = (float*)(smem + OFF_STAGE);
#pragma unroll
    for (int mt = 0; mt < 2; mt++)
#pragma unroll
        for (int nt = 0; nt < 4; nt++)
            wmma::store_matrix_sync(stage + (wm * 32 + mt * 16) * STAGE_LD + wn * 64 + nt * 16,
                                    acc[mt][nt], STAGE_LD, wmma::mem_row_major);
    __syncthreads();

    // ---- epilogue: each of 8 warps owns 8 rows; lane owns 8 cols ----
    const float* sb_bias = (const float*)(smem + OFF_BIAS);
    const float* sb_g    = (const float*)(smem + OFF_GAMMA);
    const float* sb_b    = (const float*)(smem + OFF_BETA);
    const float* sb_lw   = (const float*)(smem + OFF_LW);
    const int c0 = lane * 8;

    float bia[8], gam[8], bet[8], lwv[8];
#pragma unroll
    for (int j = 0; j < 8; j++) {
        bia[j] = sb_bias[c0 + j];
        gam[j] = sb_g[c0 + j];
        bet[j] = sb_b[c0 + j];
        if (FINAL) lwv[j] = sb_lw[c0 + j];
    }
    const float lb0 = FINAL ? __ldg(lb) : 0.f;

#pragma unroll
    for (int i = 0; i < 8; i++) {
        const int row = wid * 8 + i;
        const int gr  = rowBase + row;
        float v[8];
        float s = 0.f;
#pragma unroll
        for (int j = 0; j < 8; j++) {
            v[j] = stage[row * STAGE_LD + c0 + j] + bia[j];
            s += v[j];
        }
        s = warp_sum(s);
        const float mean = s * (1.f / 256.f);
        float q = 0.f;
#pragma unroll
        for (int j = 0; j < 8; j++) {
            float d = v[j] - mean;
            q += d * d;
        }
        q = warp_sum(q);
        const float inv = rsqrtf(q * (1.f / 256.f) + 1e-5f);

        if (!FINAL) {
            __half2 hv[4];
#pragma unroll
            for (int j = 0; j < 4; j++) {
                float za = (v[2*j]   - mean) * inv * gam[2*j]   + bet[2*j];
                float zb = (v[2*j+1] - mean) * inv * gam[2*j+1] + bet[2*j+1];
                hv[j] = __floats2half2_rn(fmaxf(za, 0.f), fmaxf(zb, 0.f));
            }
            *(uint4*)(outh + (size_t)gr * FN + c0) = *(uint4*)hv;
        } else {
            float p = 0.f;
#pragma unroll
            for (int j = 0; j < 8; j++) {
                float z = (v[j] - mean) * inv * gam[j] + bet[j];
                p = fmaf(fmaxf(z, 0.f), lwv[j], p);
            }
            p = warp_sum(p);
            if (lane == 0) outf[gr] = p + lb0;
        }
    }
}

// ============================================================
// launch: prep -> fork(gather on s2 || conv1, conv2 on stream 0) -> join
// ============================================================
extern "C" void kernel_launch(void* const* d_in, const int* in_sizes, int n_in,
                              void* d_out, int out_size) {
    const float* x   = (const float*)d_in[0];
    const float* w1  = (const float*)d_in[1];
    const float* b1  = (const float*)d_in[2];
    const float* g1  = (const float*)d_in[3];
    const float* be1 = (const float*)d_in[4];
    const float* w2  = (const float*)d_in[5];
    const float* b2  = (const float*)d_in[6];
    const float* g2  = (const float*)d_in[7];
    const float* be2 = (const float*)d_in[8];
    const float* lw  = (const float*)d_in[9];
    const float* lb  = (const float*)d_in[10];
    const int* target = (const int*)d_in[11];
    float* out = (float*)d_out;

    __half *xh, *h1h, *w1h, *w2h;
    cudaGetSymbolAddress((void**)&xh,  g_xh);
    cudaGetSymbolAddress((void**)&h1h, g_h1h);
    cudaGetSymbolAddress((void**)&w1h, g_w1h);
    cudaGetSymbolAddress((void**)&w2h, g_w2h);

    cudaFuncSetAttribute(conv_wmma_kernel<false>,
                         cudaFuncAttributeMaxDynamicSharedMemorySize, SMEM_BYTES);
    cudaFuncSetAttribute(conv_wmma_kernel<true>,
                         cudaFuncAttributeMaxDynamicSharedMemorySize, SMEM_BYTES);

    // lazy one-time stream/event creation (first call is the uncaptured
    // correctness call; captured calls only use them — GPU work identical)
    static cudaStream_t s_gather = nullptr;
    static cudaEvent_t  e_fork = nullptr, e_join = nullptr;
    if (s_gather == nullptr) {
        cudaStreamCreateWithFlags(&s_gather, cudaStreamNonBlocking);
        cudaEventCreateWithFlags(&e_fork, cudaEventDisableTiming);
        cudaEventCreateWithFlags(&e_join, cudaEventDisableTiming);
    }

    prep_kernel<<<PREP_GRID, 512>>>(w1, w2, x, target);

    // fork: gather runs concurrently with conv1 (independent data)
    cudaEventRecord(e_fork, 0);
    cudaStreamWaitEvent(s_gather, e_fork, 0);
    gather_kernel<<<GROWS / 32, 256, 0, s_gather>>>(x, out);
    cudaEventRecord(e_join, s_gather);

    conv_wmma_kernel<false><<<ROWS / BM, NTHREADS, SMEM_BYTES>>>(
        xh, w1h, b1, g1, be1, nullptr, nullptr, h1h, nullptr);
    conv_wmma_kernel<true><<<ROWS / BM, NTHREADS, SMEM_BYTES>>>(
        h1h, w2h, b2, g2, be2, lw, lb, nullptr, out + OUT_LR_ELEMS);

    // join: output not complete until gather finishes
    cudaStreamWaitEvent(0, e_join, 0);
}

// round 12
// speedup vs baseline: 1.0189x; 1.0189x over previous
#include <cuda_runtime.h>
#include <cuda_fp16.h>
#include <mma.h>
#include <cstdint>

using namespace nvcuda;

// Problem constants
#define BSZ   32
#define TN    512
#define DN    256
#define FN    256
#define ROWS  (BSZ * TN)        // 16384
#define KSUM  768               // 3 * 256
#define MEL   2048
#define GROWS (BSZ * MEL)       // 65536 gather rows
#define OUT_LR_ELEMS (BSZ * MEL * DN)   // 16777216

// GEMM tiling (fp16 m16n16k16): BM=128 x BN=256, 512 threads (16 warps, 4x4),
// warp tile 32x64, BK=64 halves, 3-stage cp.async (R6-proven pipeline).
#define BM       128
#define BKH      64
#define LDA      72              // padded leading dim in halves (144B rows)
#define NCHUNK   12              // 768 / 64
#define NSTAGE   3
#define NTHREADS 512
#define STAGE_LD 264             // fp32 epilogue stage leading dim

// ---------------- device scratch ----------------
__device__ __half g_xh[ROWS * DN];      // x in fp16 (RN)
__device__ __half g_h1h[ROWS * FN];     // conv1 out (LN+relu), fp16 (RN)
__device__ __half g_w1h[KSUM * FN];     // w transposed [f][kk], kk=k*256+d
__device__ __half g_w2h[KSUM * FN];
__device__ int    g_map[GROWS];

// ---------------- smem layout (bytes) ----------------
// per stage: A = 128 x 144B = 18432 ; B = 256 x 144B = 36864 ; stride 55296
// 3 stages = 165888. fp32 epilogue stage (128 x 264 x 4 = 135168) UNIONs at 0.
#define STG_STRIDE   55296
#define OFF_B_IN_STG 18432
#define OFF_STAGE    0
#define OFF_BIAS     165888
#define OFF_GAMMA    (OFF_BIAS  + 1024)
#define OFF_BETA     (OFF_GAMMA + 1024)
#define OFF_LW       (OFF_BETA  + 1024)
#define SMEM_BYTES   (OFF_LW + 1024)    // 169984

__device__ __forceinline__ float warp_sum(float v) {
    v += __shfl_xor_sync(0xffffffffu, v, 16);
    v += __shfl_xor_sync(0xffffffffu, v, 8);
    v += __shfl_xor_sync(0xffffffffu, v, 4);
    v += __shfl_xor_sync(0xffffffffu, v, 2);
    v += __shfl_xor_sync(0xffffffffu, v, 1);
    return v;
}

__device__ __forceinline__ void cp16(uint32_t dst, const void* src, int szbytes) {
    asm volatile("cp.async.ca.shared.global [%0], [%1], 16, %2;"
                 :: "r"(dst), "l"(src), "r"(szbytes));
}

// ============================================================
// Fused prep kernel (512 threads/block):
//   blocks [0, 384)    : convert weights (transpose + fp16)
//   blocks [384, 896)  : convert x to fp16, 4 float4/thread (MLP=4)
//   blocks [896, 928)  : per-batch duration scan -> frame map
// ============================================================
#define PREP_WB   384
#define PREP_XB   512
#define PREP_GRID (PREP_WB + PREP_XB + BSZ)

__global__ void __launch_bounds__(512)
prep_kernel(const float* __restrict__ w1, const float* __restrict__ w2,
            const float* __restrict__ x,  const int* __restrict__ target) {
    const int blk = blockIdx.x;
    if (blk < PREP_WB) {
        int i = blk * 512 + threadIdx.x;          // i < KSUM*FN
        int f  = i / KSUM;
        int kk = i - f * KSUM;
        int k  = kk >> 8;
        int d  = kk & 255;
        int src = f * KSUM + d * 3 + k;           // w[f][d][k]
        g_w1h[i] = __float2half_rn(w1[src]);
        g_w2h[i] = __float2half_rn(w2[src]);
    } else if (blk < PREP_WB + PREP_XB) {
        const int base = (blk - PREP_WB) * 2048 + threadIdx.x;  // float4 units
        float4 v[4];
#pragma unroll
        for (int k = 0; k < 4; k++)
            v[k] = ((const float4*)x)[base + k * 512];
#pragma unroll
        for (int k = 0; k < 4; k++) {
            __half2 lo = __floats2half2_rn(v[k].x, v[k].y);
            __half2 hi = __floats2half2_rn(v[k].z, v[k].w);
            uint2 pk;
            pk.x = *(uint32_t*)&lo;
            pk.y = *(uint32_t*)&hi;
            ((uint2*)g_xh)[base + k * 512] = pk;
        }
    } else {
        __shared__ int s[TN];
        const int b = blk - PREP_WB - PREP_XB;
        const int t = threadIdx.x;                 // 512 == TN
        const int dur = target[b * TN + t];
        s[t] = dur;
        __syncthreads();
        for (int off = 1; off < TN; off <<= 1) {
            int v = s[t];
            int u = (t >= off) ? s[t - off] : 0;
            __syncthreads();
            s[t] = v + u;
            __syncthreads();
        }
        const int end_   = s[t];
        const int start_ = end_ - dur;
        for (int m = t; m < MEL; m += TN) g_map[b * MEL + m] = -1;
        __syncthreads();
        if (start_ < MEL) {
            int e = end_ < MEL ? end_ : MEL;
            for (int m = start_; m < e; m++) g_map[b * MEL + m] = t;
        }
    }
}

// ============================================================
// LR gather, MLP=8 (exact fp32 copy; output 0 bit-exact)
// ============================================================
__global__ void __launch_bounds__(256)
gather_kernel(const float* __restrict__ x, float* __restrict__ out) {
    const int wid  = threadIdx.x >> 5;
    const int lane = threadIdx.x & 31;
    const int rowBase = blockIdx.x * 32 + wid * 4;   // 4 rows per warp
    const int b = rowBase >> 11;                     // / MEL

    int t[4];
#pragma unroll
    for (int r = 0; r < 4; r++) t[r] = g_map[rowBase + r];

    float4 v[8];
#pragma unroll
    for (int r = 0; r < 4; r++) {
        if (t[r] >= 0) {
            const float4* src = (const float4*)(x + (size_t)(b * TN + t[r]) * DN);
            v[r * 2]     = src[lane];
            v[r * 2 + 1] = src[lane + 32];
        } else {
            v[r * 2]     = make_float4(0.f, 0.f, 0.f, 0.f);
            v[r * 2 + 1] = make_float4(0.f, 0.f, 0.f, 0.f);
        }
    }
#pragma unroll
    for (int r = 0; r < 4; r++) {
        float4* dst = (float4*)(out + (size_t)(rowBase + r) * DN);
        dst[lane]      = v[r * 2];
        dst[lane + 32] = v[r * 2 + 1];
    }
}

// ============================================================
// fp16 wmma conv GEMM: BM=128 x 256, 512 threads (16 warps, 4x4),
// warp tile 32x64, 3-stage cp.async — R6 pipeline at doubled warp count.
// ============================================================
template <bool FINAL>
__global__ void __launch_bounds__(NTHREADS)
conv_wmma_kernel(const __half* __restrict__ in,
                 const __half* __restrict__ wh,
                 const float* __restrict__ bias,
                 const float* __restrict__ gamma,
                 const float* __restrict__ beta,
                 const float* __restrict__ lw,
                 const float* __restrict__ lb,
                 __half* __restrict__ outh,
                 float* __restrict__ outf) {
    extern __shared__ char smem[];
    const uint32_t sbase = (uint32_t)__cvta_generic_to_shared(smem);
    const int tid  = threadIdx.x;
    const int wid  = tid >> 5;
    const int lane = tid & 31;
    const int wm   = wid & 3;          // warp row group (0..3) -> 32 rows
    const int wn   = wid >> 2;         // warp col group (0..3) -> 64 cols
    const int rowBase = blockIdx.x * BM;

    // stage params
    if (tid < 256) {
        ((float*)(smem + OFF_BIAS))[tid]  = bias[tid];
        ((float*)(smem + OFF_GAMMA))[tid] = gamma[tid];
        ((float*)(smem + OFF_BETA))[tid]  = beta[tid];
        if (FINAL) ((float*)(smem + OFF_LW))[tid] = lw[tid];
    }

    wmma::fragment<wmma::accumulator, 16, 16, 16, float> acc[2][4];
#pragma unroll
    for (int mt = 0; mt < 2; mt++)
#pragma unroll
        for (int nt = 0; nt < 4; nt++) wmma::fill_fragment(acc[mt][nt], 0.f);

    auto load_tiles = [&](int c) {
        const int slot = c % NSTAGE;
        const uint32_t As = sbase + slot * STG_STRIDE;
        const uint32_t Bs = As + OFF_B_IN_STG;
        const int k   = c >> 2;
        const int d0  = (c & 3) << 6;
        const int km1 = k - 1;
#pragma unroll
        for (int i = 0; i < 2; i++) {      // A: 1024 16B units
            const int u   = i * NTHREADS + tid;
            const int row = u >> 3, seg = u & 7;
            const int gr  = rowBase + row;
            const int tpos = (gr & (TN - 1)) + km1;
            const bool p = (tpos >= 0 && tpos < TN);
            const __half* src = p ? (in + (size_t)(gr + km1) * DN + d0 + seg * 8) : in;
            cp16(As + row * (LDA * 2) + seg * 16, src, p ? 16 : 0);
        }
#pragma unroll
        for (int i = 0; i < 4; i++) {      // B: 2048 16B units
            const int u = i * NTHREADS + tid;
            const int f = u >> 3, seg = u & 7;
            cp16(Bs + f * (LDA * 2) + seg * 16,
                 wh + (size_t)f * KSUM + c * BKH + seg * 8, 16);
        }
        asm volatile("cp.async.commit_group;" ::: "memory");
    };

    load_tiles(0);
    load_tiles(1);

    for (int c = 0; c < NCHUNK; c++) {
        if (c < NCHUNK - 1) {
            asm volatile("cp.async.wait_group 1;" ::: "memory");
        } else {
            asm volatile("cp.async.wait_group 0;" ::: "memory");
        }
        __syncthreads();
        if (c + 2 < NCHUNK) load_tiles(c + 2);

        const int slot = c % NSTAGE;
        const __half* As = (const __half*)(smem + slot * STG_STRIDE);
        const __half* Bs = (const __half*)(smem + slot * STG_STRIDE + OFF_B_IN_STG);
#pragma unroll
        for (int ks = 0; ks < 4; ks++) {
            wmma::fragment<wmma::matrix_a, 16, 16, 16, __half, wmma::row_major> af[2];
            wmma::fragment<wmma::matrix_b, 16, 16, 16, __half, wmma::col_major> bf[4];
#pragma unroll
            for (int mt = 0; mt < 2; mt++)
                wmma::load_matrix_sync(af[mt], As + (wm * 32 + mt * 16) * LDA + ks * 16, LDA);
#pragma unroll
            for (int nt = 0; nt < 4; nt++)
                wmma::load_matrix_sync(bf[nt], Bs + (wn * 64 + nt * 16) * LDA + ks * 16, LDA);
#pragma unroll
            for (int mt = 0; mt < 2; mt++)
#pragma unroll
                for (int nt = 0; nt < 4; nt++)
                    wmma::mma_sync(acc[mt][nt], af[mt], bf[nt], acc[mt][nt]);
        }
    }
    __syncthreads();   // tiles dead; reuse smem as fp32 stage

    // ---- stage accumulators to smem ----
    float* stage = (float*)(smem + OFF_STAGE);
#pragma unroll
    for (int mt = 0; mt < 2; mt++)
#pragma unroll
        for (int nt = 0; nt < 4; nt++)
            wmma::store_matrix_sync(stage + (wm * 32 + mt * 16) * STAGE_LD + wn * 64 + nt * 16,
                                    acc[mt][nt], STAGE_LD, wmma::mem_row_major);
    __syncthreads();

    // ---- epilogue: each of 16 warps owns 8 rows; lane owns 8 cols ----
    const float* sb_bias = (const float*)(smem + OFF_BIAS);
    const float* sb_g    = (const float*)(smem + OFF_GAMMA);
    const float* sb_b    = (const float*)(smem + OFF_BETA);
    const float* sb_lw   = (const float*)(smem + OFF_LW);
    const int c0 = lane * 8;

    float bia[8], gam[8], bet[8], lwv[8];
#pragma unroll
    for (int j = 0; j < 8; j++) {
        bia[j] = sb_bias[c0 + j];
        gam[j] = sb_g[c0 + j];
        bet[j] = sb_b[c0 + j];
        if (FINAL) lwv[j] = sb_lw[c0 + j];
    }
    const float lb0 = FINAL ? __ldg(lb) : 0.f;

#pragma unroll
    for (int i = 0; i < 8; i++) {
        const int row = wid * 8 + i;
        const int gr  = rowBase + row;
        float v[8];
        float s = 0.f;
#pragma unroll
        for (int j = 0; j < 8; j++) {
            v[j] = stage[row * STAGE_LD + c0 + j] + bia[j];
            s += v[j];
        }
        s = warp_sum(s);
        const float mean = s * (1.f / 256.f);
        float q = 0.f;
#pragma unroll
        for (int j = 0; j < 8; j++) {
            float d = v[j] - mean;
            q += d * d;
        }
        q = warp_sum(q);
        const float inv = rsqrtf(q * (1.f / 256.f) + 1e-5f);

        if (!FINAL) {
            __half2 hv[4];
#pragma unroll
            for (int j = 0; j < 4; j++) {
                float za = (v[2*j]   - mean) * inv * gam[2*j]   + bet[2*j];
                float zb = (v[2*j+1] - mean) * inv * gam[2*j+1] + bet[2*j+1];
                hv[j] = __floats2half2_rn(fmaxf(za, 0.f), fmaxf(zb, 0.f));
            }
            *(uint4*)(outh + (size_t)gr * FN + c0) = *(uint4*)hv;
        } else {
            float p = 0.f;
#pragma unroll
            for (int j = 0; j < 8; j++) {
                float z = (v[j] - mean) * inv * gam[j] + bet[j];
                p = fmaf(fmaxf(z, 0.f), lwv[j], p);
            }
            p = warp_sum(p);
            if (lane == 0) outf[gr] = p + lb0;
        }
    }
}

// ============================================================
// launch: prep -> fork(gather || conv1, conv2) -> join
// ============================================================
extern "C" void kernel_launch(void* const* d_in, const int* in_sizes, int n_in,
                              void* d_out, int out_size) {
    const float* x   = (const float*)d_in[0];
    const float* w1  = (const float*)d_in[1];
    const float* b1  = (const float*)d_in[2];
    const float* g1  = (const float*)d_in[3];
    const float* be1 = (const float*)d_in[4];
    const float* w2  = (const float*)d_in[5];
    const float* b2  = (const float*)d_in[6];
    const float* g2  = (const float*)d_in[7];
    const float* be2 = (const float*)d_in[8];
    const float* lw  = (const float*)d_in[9];
    const float* lb  = (const float*)d_in[10];
    const int* target = (const int*)d_in[11];
    float* out = (float*)d_out;

    __half *xh, *h1h, *w1h, *w2h;
    cudaGetSymbolAddress((void**)&xh,  g_xh);
    cudaGetSymbolAddress((void**)&h1h, g_h1h);
    cudaGetSymbolAddress((void**)&w1h, g_w1h);
    cudaGetSymbolAddress((void**)&w2h, g_w2h);

    cudaFuncSetAttribute(conv_wmma_kernel<false>,
                         cudaFuncAttributeMaxDynamicSharedMemorySize, SMEM_BYTES);
    cudaFuncSetAttribute(conv_wmma_kernel<true>,
                         cudaFuncAttributeMaxDynamicSharedMemorySize, SMEM_BYTES);

    // lazy one-time stream/event creation (first call is the uncaptured
    // correctness call; captured calls only use them — GPU work identical)
    static cudaStream_t s_gather = nullptr;
    static cudaEvent_t  e_fork = nullptr, e_join = nullptr;
    if (s_gather == nullptr) {
        cudaStreamCreateWithFlags(&s_gather, cudaStreamNonBlocking);
        cudaEventCreateWithFlags(&e_fork, cudaEventDisableTiming);
        cudaEventCreateWithFlags(&e_join, cudaEventDisableTiming);
    }

    prep_kernel<<<PREP_GRID, 512>>>(w1, w2, x, target);

    // fork: gather runs concurrently with conv1 (independent data)
    cudaEventRecord(e_fork, 0);
    cudaStreamWaitEvent(s_gather, e_fork, 0);
    gather_kernel<<<GROWS / 32, 256, 0, s_gather>>>(x, out);
    cudaEventRecord(e_join, s_gather);

    conv_wmma_kernel<false><<<ROWS / BM, NTHREADS, SMEM_BYTES>>>(
        xh, w1h, b1, g1, be1, nullptr, nullptr, h1h, nullptr);
    conv_wmma_kernel<true><<<ROWS / BM, NTHREADS, SMEM_BYTES>>>(
        h1h, w2h, b2, g2, be2, lw, lb, nullptr, out + OUT_LR_ELEMS);

    // join: output not complete until gather finishes
    cudaStreamWaitEvent(0, e_join, 0);
}

// round 13
// speedup vs baseline: 1.1161x; 1.0955x over previous
#include <cuda_runtime.h>
#include <cuda_fp16.h>
#include <mma.h>
#include <cstdint>

using namespace nvcuda;

// Problem constants
#define BSZ   32
#define TN    512
#define DN    256
#define FN    256
#define ROWS  (BSZ * TN)        // 16384
#define KSUM  768               // 3 * 256
#define MEL   2048
#define GROWS (BSZ * MEL)       // 65536 gather rows
#define OUT_LR_ELEMS (BSZ * MEL * DN)   // 16777216

// GEMM tiling (fp16 m16n16k16): BM=128 x BN=256, 256 threads (8 warps, 2x4),
// warp tile 64x64, BK=64 halves, 3-stage cp.async — R9's best-measured config.
#define BM       128
#define BKH      64
#define LDA      72              // padded leading dim in halves (144B rows)
#define NCHUNK   12              // 768 / 64
#define NSTAGE   3
#define NTHREADS 256
#define STAGE_LD 264             // fp32 epilogue stage leading dim

// ---------------- device scratch ----------------
__device__ __half g_xh[ROWS * DN];      // x in fp16 (RN)
__device__ __half g_h1h[ROWS * FN];     // conv1 out (LN+relu), fp16 (RN)
__device__ __half g_w1h[KSUM * FN];     // w transposed [f][kk], kk=k*256+d
__device__ __half g_w2h[KSUM * FN];
__device__ int    g_map[GROWS];

// ---------------- smem layout (bytes) ----------------
#define STG_STRIDE   55296
#define OFF_B_IN_STG 18432
#define OFF_STAGE    0
#define OFF_BIAS     165888
#define OFF_GAMMA    (OFF_BIAS  + 1024)
#define OFF_BETA     (OFF_GAMMA + 1024)
#define OFF_LW       (OFF_BETA  + 1024)
#define SMEM_BYTES   (OFF_LW + 1024)    // 169984

__device__ __forceinline__ float warp_sum(float v) {
    v += __shfl_xor_sync(0xffffffffu, v, 16);
    v += __shfl_xor_sync(0xffffffffu, v, 8);
    v += __shfl_xor_sync(0xffffffffu, v, 4);
    v += __shfl_xor_sync(0xffffffffu, v, 2);
    v += __shfl_xor_sync(0xffffffffu, v, 1);
    return v;
}

__device__ __forceinline__ void cp16(uint32_t dst, const void* src, int szbytes) {
    asm volatile("cp.async.ca.shared.global [%0], [%1], 16, %2;"
                 :: "r"(dst), "l"(src), "r"(szbytes));
}

// ============================================================
// Weight convert (both convs): transpose + fp16. 384 blocks x 512.
// ============================================================
__global__ void __launch_bounds__(512)
wconv_kernel(const float* __restrict__ w1, const float* __restrict__ w2) {
    int i = blockIdx.x * 512 + threadIdx.x;   // i < KSUM*FN
    int f  = i / KSUM;
    int kk = i - f * KSUM;
    int k  = kk >> 8;
    int d  = kk & 255;
    int src = f * KSUM + d * 3 + k;           // w[f][d][k]
    g_w1h[i] = __float2half_rn(w1[src]);
    g_w2h[i] = __float2half_rn(w2[src]);
}

// ============================================================
// x convert: fp32 -> fp16, 4 float4/thread (MLP=4). 512 blocks x 512.
// ============================================================
__global__ void __launch_bounds__(512)
xconv_kernel(const float* __restrict__ x) {
    const int base = blockIdx.x * 2048 + threadIdx.x;  // float4 units
    float4 v[4];
#pragma unroll
    for (int k = 0; k < 4; k++)
        v[k] = ((const float4*)x)[base + k * 512];
#pragma unroll
    for (int k = 0; k < 4; k++) {
        __half2 lo = __floats2half2_rn(v[k].x, v[k].y);
        __half2 hi = __floats2half2_rn(v[k].z, v[k].w);
        uint2 pk;
        pk.x = *(uint32_t*)&lo;
        pk.y = *(uint32_t*)&hi;
        ((uint2*)g_xh)[base + k * 512] = pk;
    }
}

// ============================================================
// Per-batch duration scan -> frame map. 32 blocks x 512.
// ============================================================
__global__ void __launch_bounds__(512)
map_kernel(const int* __restrict__ target) {
    __shared__ int s[TN];
    const int b = blockIdx.x;
    const int t = threadIdx.x;                 // 512 == TN
    const int dur = target[b * TN + t];
    s[t] = dur;
    __syncthreads();
    for (int off = 1; off < TN; off <<= 1) {
        int v = s[t];
        int u = (t >= off) ? s[t - off] : 0;
        __syncthreads();
        s[t] = v + u;
        __syncthreads();
    }
    const int end_   = s[t];
    const int start_ = end_ - dur;
    for (int m = t; m < MEL; m += TN) g_map[b * MEL + m] = -1;
    __syncthreads();
    if (start_ < MEL) {
        int e = end_ < MEL ? end_ : MEL;
        for (int m = start_; m < e; m++) g_map[b * MEL + m] = t;
    }
}

// ============================================================
// LR gather, MLP=8 (exact fp32 copy; output 0 bit-exact)
// ============================================================
__global__ void __launch_bounds__(256)
gather_kernel(const float* __restrict__ x, float* __restrict__ out) {
    const int wid  = threadIdx.x >> 5;
    const int lane = threadIdx.x & 31;
    const int rowBase = blockIdx.x * 32 + wid * 4;   // 4 rows per warp
    const int b = rowBase >> 11;                     // / MEL

    int t[4];
#pragma unroll
    for (int r = 0; r < 4; r++) t[r] = g_map[rowBase + r];

    float4 v[8];
#pragma unroll
    for (int r = 0; r < 4; r++) {
        if (t[r] >= 0) {
            const float4* src = (const float4*)(x + (size_t)(b * TN + t[r]) * DN);
            v[r * 2]     = src[lane];
            v[r * 2 + 1] = src[lane + 32];
        } else {
            v[r * 2]     = make_float4(0.f, 0.f, 0.f, 0.f);
            v[r * 2 + 1] = make_float4(0.f, 0.f, 0.f, 0.f);
        }
    }
#pragma unroll
    for (int r = 0; r < 4; r++) {
        float4* dst = (float4*)(out + (size_t)(rowBase + r) * DN);
        dst[lane]      = v[r * 2];
        dst[lane + 32] = v[r * 2 + 1];
    }
}

// ============================================================
// fp16 wmma conv GEMM (R9's exact best-measured core):
// 256 threads, 8 warps (2x4), warp tile 64x64, 3-stage cp.async.
// ============================================================
template <bool FINAL>
__global__ void __launch_bounds__(NTHREADS)
conv_wmma_kernel(const __half* __restrict__ in,
                 const __half* __restrict__ wh,
                 const float* __restrict__ bias,
                 const float* __restrict__ gamma,
                 const float* __restrict__ beta,
                 const float* __restrict__ lw,
                 const float* __restrict__ lb,
                 __half* __restrict__ outh,
                 float* __restrict__ outf) {
    extern __shared__ char smem[];
    const uint32_t sbase = (uint32_t)__cvta_generic_to_shared(smem);
    const int tid  = threadIdx.x;
    const int wid  = tid >> 5;
    const int lane = tid & 31;
    const int wm   = wid & 1;          // warp row group -> 64 rows
    const int wn   = wid >> 1;         // warp col group -> 64 cols
    const int rowBase = blockIdx.x * BM;

    // stage params
    ((float*)(smem + OFF_BIAS))[tid]  = bias[tid];
    ((float*)(smem + OFF_GAMMA))[tid] = gamma[tid];
    ((float*)(smem + OFF_BETA))[tid]  = beta[tid];
    if (FINAL) ((float*)(smem + OFF_LW))[tid] = lw[tid];

    wmma::fragment<wmma::accumulator, 16, 16, 16, float> acc[4][4];
#pragma unroll
    for (int mt = 0; mt < 4; mt++)
#pragma unroll
        for (int nt = 0; nt < 4; nt++) wmma::fill_fragment(acc[mt][nt], 0.f);

    auto load_tiles = [&](int c) {
        const int slot = c % NSTAGE;
        const uint32_t As = sbase + slot * STG_STRIDE;
        const uint32_t Bs = As + OFF_B_IN_STG;
        const int k   = c >> 2;
        const int d0  = (c & 3) << 6;
        const int km1 = k - 1;
#pragma unroll
        for (int i = 0; i < 4; i++) {      // A: 1024 16B units
            const int u   = i * NTHREADS + tid;
            const int row = u >> 3, seg = u & 7;
            const int gr  = rowBase + row;
            const int tpos = (gr & (TN - 1)) + km1;
            const bool p = (tpos >= 0 && tpos < TN);
            const __half* src = p ? (in + (size_t)(gr + km1) * DN + d0 + seg * 8) : in;
            cp16(As + row * (LDA * 2) + seg * 16, src, p ? 16 : 0);
        }
#pragma unroll
        for (int i = 0; i < 8; i++) {      // B: 2048 16B units
            const int u = i * NTHREADS + tid;
            const int f = u >> 3, seg = u & 7;
            cp16(Bs + f * (LDA * 2) + seg * 16,
                 wh + (size_t)f * KSUM + c * BKH + seg * 8, 16);
        }
        asm volatile("cp.async.commit_group;" ::: "memory");
    };

    load_tiles(0);
    load_tiles(1);

    for (int c = 0; c < NCHUNK; c++) {
        if (c < NCHUNK - 1) {
            asm volatile("cp.async.wait_group 1;" ::: "memory");
        } else {
            asm volatile("cp.async.wait_group 0;" ::: "memory");
        }
        __syncthreads();
        if (c + 2 < NCHUNK) load_tiles(c + 2);

        const int slot = c % NSTAGE;
        const __half* As = (const __half*)(smem + slot * STG_STRIDE);
        const __half* Bs = (const __half*)(smem + slot * STG_STRIDE + OFF_B_IN_STG);
#pragma unroll
        for (int ks = 0; ks < 4; ks++) {
            wmma::fragment<wmma::matrix_a, 16, 16, 16, __half, wmma::row_major> af[4];
            wmma::fragment<wmma::matrix_b, 16, 16, 16, __half, wmma::col_major> bf[4];
#pragma unroll
            for (int mt = 0; mt < 4; mt++)
                wmma::load_matrix_sync(af[mt], As + (wm * 64 + mt * 16) * LDA + ks * 16, LDA);
#pragma unroll
            for (int nt = 0; nt < 4; nt++)
                wmma::load_matrix_sync(bf[nt], Bs + (wn * 64 + nt * 16) * LDA + ks * 16, LDA);
#pragma unroll
            for (int mt = 0; mt < 4; mt++)
#pragma unroll
                for (int nt = 0; nt < 4; nt++)
                    wmma::mma_sync(acc[mt][nt], af[mt], bf[nt], acc[mt][nt]);
        }
    }
    __syncthreads();   // tiles dead; reuse smem as fp32 stage

    // ---- stage accumulators to smem ----
    float* stage = (float*)(smem + OFF_STAGE);
#pragma unroll
    for (int mt = 0; mt < 4; mt++)
#pragma unroll
        for (int nt = 0; nt < 4; nt++)
            wmma::store_matrix_sync(stage + (wm * 64 + mt * 16) * STAGE_LD + wn * 64 + nt * 16,
                                    acc[mt][nt], STAGE_LD, wmma::mem_row_major);
    __syncthreads();

    // ---- epilogue: each of 8 warps owns 16 rows; lane owns 8 cols ----
    const float* sb_bias = (const float*)(smem + OFF_BIAS);
    const float* sb_g    = (const float*)(smem + OFF_GAMMA);
    const float* sb_b    = (const float*)(smem + OFF_BETA);
    const float* sb_lw   = (const float*)(smem + OFF_LW);
    const int c0 = lane * 8;

    float bia[8], gam[8], bet[8], lwv[8];
#pragma unroll
    for (int j = 0; j < 8; j++) {
        bia[j] = sb_bias[c0 + j];
        gam[j] = sb_g[c0 + j];
        bet[j] = sb_b[c0 + j];
        if (FINAL) lwv[j] = sb_lw[c0 + j];
    }
    const float lb0 = FINAL ? __ldg(lb) : 0.f;

#pragma unroll
    for (int i = 0; i < 16; i++) {
        const int row = wid * 16 + i;
        const int gr  = rowBase + row;
        float v[8];
        float s = 0.f;
#pragma unroll
        for (int j = 0; j < 8; j++) {
            v[j] = stage[row * STAGE_LD + c0 + j] + bia[j];
            s += v[j];
        }
        s = warp_sum(s);
        const float mean = s * (1.f / 256.f);
        float q = 0.f;
#pragma unroll
        for (int j = 0; j < 8; j++) {
            float d = v[j] - mean;
            q += d * d;
        }
        q = warp_sum(q);
        const float inv = rsqrtf(q * (1.f / 256.f) + 1e-5f);

        if (!FINAL) {
            __half2 hv[4];
#pragma unroll
            for (int j = 0; j < 4; j++) {
                float za = (v[2*j]   - mean) * inv * gam[2*j]   + bet[2*j];
                float zb = (v[2*j+1] - mean) * inv * gam[2*j+1] + bet[2*j+1];
                hv[j] = __floats2half2_rn(fmaxf(za, 0.f), fmaxf(zb, 0.f));
            }
            *(uint4*)(outh + (size_t)gr * FN + c0) = *(uint4*)hv;
        } else {
            float p = 0.f;
#pragma unroll
            for (int j = 0; j < 8; j++) {
                float z = (v[j] - mean) * inv * gam[j] + bet[j];
                p = fmaf(fmaxf(z, 0.f), lwv[j], p);
            }
            p = warp_sum(p);
            if (lane == 0) outf[gr] = p + lb0;
        }
    }
}

// ============================================================
// launch:
//   stream 0 : xconv -> wait(wconv) -> conv1 -> conv2 -> wait(gather)
//   stream A : wconv (weights, concurrent with xconv)
//   stream B : map -> gather (fully off critical path)
// ============================================================
extern "C" void kernel_launch(void* const* d_in, const int* in_sizes, int n_in,
                              void* d_out, int out_size) {
    const float* x   = (const float*)d_in[0];
    const float* w1  = (const float*)d_in[1];
    const float* b1  = (const float*)d_in[2];
    const float* g1  = (const float*)d_in[3];
    const float* be1 = (const float*)d_in[4];
    const float* w2  = (const float*)d_in[5];
    const float* b2  = (const float*)d_in[6];
    const float* g2  = (const float*)d_in[7];
    const float* be2 = (const float*)d_in[8];
    const float* lw  = (const float*)d_in[9];
    const float* lb  = (const float*)d_in[10];
    const int* target = (const int*)d_in[11];
    float* out = (float*)d_out;

    __half *xh, *h1h, *w1h, *w2h;
    cudaGetSymbolAddress((void**)&xh,  g_xh);
    cudaGetSymbolAddress((void**)&h1h, g_h1h);
    cudaGetSymbolAddress((void**)&w1h, g_w1h);
    cudaGetSymbolAddress((void**)&w2h, g_w2h);

    cudaFuncSetAttribute(conv_wmma_kernel<false>,
                         cudaFuncAttributeMaxDynamicSharedMemorySize, SMEM_BYTES);
    cudaFuncSetAttribute(conv_wmma_kernel<true>,
                         cudaFuncAttributeMaxDynamicSharedMemorySize, SMEM_BYTES);

    // lazy one-time stream/event creation (first call is the uncaptured
    // correctness call; captured calls only use them — GPU work identical)
    static cudaStream_t sA = nullptr, sB = nullptr;
    static cudaEvent_t  e_fork = nullptr, e_w = nullptr, e_g = nullptr;
    if (sA == nullptr) {
        cudaStreamCreateWithFlags(&sA, cudaStreamNonBlocking);
        cudaStreamCreateWithFlags(&sB, cudaStreamNonBlocking);
        cudaEventCreateWithFlags(&e_fork, cudaEventDisableTiming);
        cudaEventCreateWithFlags(&e_w,    cudaEventDisableTiming);
        cudaEventCreateWithFlags(&e_g,    cudaEventDisableTiming);
    }

    // fork point
    cudaEventRecord(e_fork, 0);
    cudaStreamWaitEvent(sA, e_fork, 0);
    cudaStreamWaitEvent(sB, e_fork, 0);

    // stream A: weight conversion (needed before conv1/conv2)
    wconv_kernel<<<KSUM * FN / 512, 512, 0, sA>>>(w1, w2);
    cudaEventRecord(e_w, sA);

    // stream B: map -> gather (independent of conv path; writes output 0)
    map_kernel<<<BSZ, TN, 0, sB>>>(target);
    gather_kernel<<<GROWS / 32, 256, 0, sB>>>(x, out);
    cudaEventRecord(e_g, sB);

    // stream 0: x conversion, then convs once weights are ready
    xconv_kernel<<<ROWS * DN / 4 / 2048, 512>>>(x);
    cudaStreamWaitEvent(0, e_w, 0);

    conv_wmma_kernel<false><<<ROWS / BM, NTHREADS, SMEM_BYTES>>>(
        xh, w1h, b1, g1, be1, nullptr, nullptr, h1h, nullptr);
    conv_wmma_kernel<true><<<ROWS / BM, NTHREADS, SMEM_BYTES>>>(
        h1h, w2h, b2, g2, be2, lw, lb, nullptr, out + OUT_LR_ELEMS);

    // join: output 0 not complete until gather finishes
    cudaStreamWaitEvent(0, e_g, 0);
}

// round 14
// speedup vs baseline: 1.1176x; 1.0014x over previous
#include <cuda_runtime.h>
#include <cuda_fp16.h>
#include <mma.h>
#include <cstdint>

using namespace nvcuda;

// Problem constants
#define BSZ   32
#define TN    512
#define DN    256
#define FN    256
#define ROWS  (BSZ * TN)        // 16384
#define KSUM  768               // 3 * 256
#define MEL   2048
#define GROWS (BSZ * MEL)       // 65536 gather rows
#define OUT_LR_ELEMS (BSZ * MEL * DN)   // 16777216

// GEMM tiling (fp16 m16n16k16): BM=128 x BN=256, 256 threads (8 warps, 2x4),
// warp tile 64x64, BK=64 halves, 3-stage cp.async — R9's best-measured config.
#define BM       128
#define BKH      64
#define LDA      72              // padded leading dim in halves (144B rows)
#define NCHUNK   12              // 768 / 64
#define NSTAGE   3
#define NTHREADS 256
#define STAGE_LD 264             // fp32 epilogue stage leading dim

// ---------------- device scratch ----------------
__device__ __half g_xh[ROWS * DN];      // x in fp16 (RN)
__device__ __half g_h1h[ROWS * FN];     // conv1 out (LN+relu), fp16 (RN)
__device__ __half g_w1h[KSUM * FN];     // w transposed [f][kk], kk=k*256+d
__device__ __half g_w2h[KSUM * FN];
__device__ int    g_map[GROWS];

// ---------------- smem layout (bytes) ----------------
#define STG_STRIDE   55296
#define OFF_B_IN_STG 18432
#define OFF_STAGE    0
#define OFF_BIAS     165888
#define OFF_GAMMA    (OFF_BIAS  + 1024)
#define OFF_BETA     (OFF_GAMMA + 1024)
#define OFF_LW       (OFF_BETA  + 1024)
#define SMEM_BYTES   (OFF_LW + 1024)    // 169984

__device__ __forceinline__ float warp_sum(float v) {
    v += __shfl_xor_sync(0xffffffffu, v, 16);
    v += __shfl_xor_sync(0xffffffffu, v, 8);
    v += __shfl_xor_sync(0xffffffffu, v, 4);
    v += __shfl_xor_sync(0xffffffffu, v, 2);
    v += __shfl_xor_sync(0xffffffffu, v, 1);
    return v;
}

__device__ __forceinline__ void cp16(uint32_t dst, const void* src, int szbytes) {
    asm volatile("cp.async.ca.shared.global [%0], [%1], 16, %2;"
                 :: "r"(dst), "l"(src), "r"(szbytes));
}

// ============================================================
// Weight convert (both convs): transpose + fp16. 384 blocks x 512.
// ============================================================
__global__ void __launch_bounds__(512)
wconv_kernel(const float* __restrict__ w1, const float* __restrict__ w2) {
    int i = blockIdx.x * 512 + threadIdx.x;   // i < KSUM*FN
    int f  = i / KSUM;
    int kk = i - f * KSUM;
    int k  = kk >> 8;
    int d  = kk & 255;
    int src = f * KSUM + d * 3 + k;           // w[f][d][k]
    g_w1h[i] = __float2half_rn(w1[src]);
    g_w2h[i] = __float2half_rn(w2[src]);
}

// ============================================================
// x convert: fp32 -> fp16, MLP=8. 256 blocks x 512 threads.
// Each thread: 8 LDG.128 (batched), 4 STG.128 (paired halves).
// ============================================================
__global__ void __launch_bounds__(512)
xconv_kernel(const float* __restrict__ x) {
    const float4* x4 = (const float4*)x;
    uint4* o4 = (uint4*)g_xh;
    const int b4 = blockIdx.x * 4096 + threadIdx.x * 2;   // float4 units

    float4 v[8];
#pragma unroll
    for (int p = 0; p < 4; p++) {
        v[2 * p]     = x4[b4 + p * 1024];
        v[2 * p + 1] = x4[b4 + p * 1024 + 1];
    }
#pragma unroll
    for (int p = 0; p < 4; p++) {
        const float4 a = v[2 * p], bq = v[2 * p + 1];
        __half2 h0 = __floats2half2_rn(a.x, a.y);
        __half2 h1 = __floats2half2_rn(a.z, a.w);
        __half2 h2 = __floats2half2_rn(bq.x, bq.y);
        __half2 h3 = __floats2half2_rn(bq.z, bq.w);
        uint4 pk;
        pk.x = *(uint32_t*)&h0;
        pk.y = *(uint32_t*)&h1;
        pk.z = *(uint32_t*)&h2;
        pk.w = *(uint32_t*)&h3;
        o4[blockIdx.x * 2048 + p * 512 + threadIdx.x] = pk;
    }
}

// ============================================================
// Per-batch duration scan -> frame map. 32 blocks x 512.
// ============================================================
__global__ void __launch_bounds__(512)
map_kernel(const int* __restrict__ target) {
    __shared__ int s[TN];
    const int b = blockIdx.x;
    const int t = threadIdx.x;                 // 512 == TN
    const int dur = target[b * TN + t];
    s[t] = dur;
    __syncthreads();
    for (int off = 1; off < TN; off <<= 1) {
        int v = s[t];
        int u = (t >= off) ? s[t - off] : 0;
        __syncthreads();
        s[t] = v + u;
        __syncthreads();
    }
    const int end_   = s[t];
    const int start_ = end_ - dur;
    for (int m = t; m < MEL; m += TN) g_map[b * MEL + m] = -1;
    __syncthreads();
    if (start_ < MEL) {
        int e = end_ < MEL ? end_ : MEL;
        for (int m = start_; m < e; m++) g_map[b * MEL + m] = t;
    }
}

// ============================================================
// LR gather, MLP=8 (exact fp32 copy; output 0 bit-exact)
// ============================================================
__global__ void __launch_bounds__(256)
gather_kernel(const float* __restrict__ x, float* __restrict__ out) {
    const int wid  = threadIdx.x >> 5;
    const int lane = threadIdx.x & 31;
    const int rowBase = blockIdx.x * 32 + wid * 4;   // 4 rows per warp
    const int b = rowBase >> 11;                     // / MEL

    int t[4];
#pragma unroll
    for (int r = 0; r < 4; r++) t[r] = g_map[rowBase + r];

    float4 v[8];
#pragma unroll
    for (int r = 0; r < 4; r++) {
        if (t[r] >= 0) {
            const float4* src = (const float4*)(x + (size_t)(b * TN + t[r]) * DN);
            v[r * 2]     = src[lane];
            v[r * 2 + 1] = src[lane + 32];
        } else {
            v[r * 2]     = make_float4(0.f, 0.f, 0.f, 0.f);
            v[r * 2 + 1] = make_float4(0.f, 0.f, 0.f, 0.f);
        }
    }
#pragma unroll
    for (int r = 0; r < 4; r++) {
        float4* dst = (float4*)(out + (size_t)(rowBase + r) * DN);
        dst[lane]      = v[r * 2];
        dst[lane + 32] = v[r * 2 + 1];
    }
}

// ============================================================
// fp16 wmma conv GEMM (R9's exact best-measured core):
// 256 threads, 8 warps (2x4), warp tile 64x64, 3-stage cp.async.
// ============================================================
template <bool FINAL>
__global__ void __launch_bounds__(NTHREADS)
conv_wmma_kernel(const __half* __restrict__ in,
                 const __half* __restrict__ wh,
                 const float* __restrict__ bias,
                 const float* __restrict__ gamma,
                 const float* __restrict__ beta,
                 const float* __restrict__ lw,
                 const float* __restrict__ lb,
                 __half* __restrict__ outh,
                 float* __restrict__ outf) {
    extern __shared__ char smem[];
    const uint32_t sbase = (uint32_t)__cvta_generic_to_shared(smem);
    const int tid  = threadIdx.x;
    const int wid  = tid >> 5;
    const int lane = tid & 31;
    const int wm   = wid & 1;          // warp row group -> 64 rows
    const int wn   = wid >> 1;         // warp col group -> 64 cols
    const int rowBase = blockIdx.x * BM;

    // stage params
    ((float*)(smem + OFF_BIAS))[tid]  = bias[tid];
    ((float*)(smem + OFF_GAMMA))[tid] = gamma[tid];
    ((float*)(smem + OFF_BETA))[tid]  = beta[tid];
    if (FINAL) ((float*)(smem + OFF_LW))[tid] = lw[tid];

    wmma::fragment<wmma::accumulator, 16, 16, 16, float> acc[4][4];
#pragma unroll
    for (int mt = 0; mt < 4; mt++)
#pragma unroll
        for (int nt = 0; nt < 4; nt++) wmma::fill_fragment(acc[mt][nt], 0.f);

    auto load_tiles = [&](int c) {
        const int slot = c % NSTAGE;
        const uint32_t As = sbase + slot * STG_STRIDE;
        const uint32_t Bs = As + OFF_B_IN_STG;
        const int k   = c >> 2;
        const int d0  = (c & 3) << 6;
        const int km1 = k - 1;
#pragma unroll
        for (int i = 0; i < 4; i++) {      // A: 1024 16B units
            const int u   = i * NTHREADS + tid;
            const int row = u >> 3, seg = u & 7;
            const int gr  = rowBase + row;
            const int tpos = (gr & (TN - 1)) + km1;
            const bool p = (tpos >= 0 && tpos < TN);
            const __half* src = p ? (in + (size_t)(gr + km1) * DN + d0 + seg * 8) : in;
            cp16(As + row * (LDA * 2) + seg * 16, src, p ? 16 : 0);
        }
#pragma unroll
        for (int i = 0; i < 8; i++) {      // B: 2048 16B units
            const int u = i * NTHREADS + tid;
            const int f = u >> 3, seg = u & 7;
            cp16(Bs + f * (LDA * 2) + seg * 16,
                 wh + (size_t)f * KSUM + c * BKH + seg * 8, 16);
        }
        asm volatile("cp.async.commit_group;" ::: "memory");
    };

    load_tiles(0);
    load_tiles(1);

    for (int c = 0; c < NCHUNK; c++) {
        if (c < NCHUNK - 1) {
            asm volatile("cp.async.wait_group 1;" ::: "memory");
        } else {
            asm volatile("cp.async.wait_group 0;" ::: "memory");
        }
        __syncthreads();
        if (c + 2 < NCHUNK) load_tiles(c + 2);

        const int slot = c % NSTAGE;
        const __half* As = (const __half*)(smem + slot * STG_STRIDE);
        const __half* Bs = (const __half*)(smem + slot * STG_STRIDE + OFF_B_IN_STG);
#pragma unroll
        for (int ks = 0; ks < 4; ks++) {
            wmma::fragment<wmma::matrix_a, 16, 16, 16, __half, wmma::row_major> af[4];
            wmma::fragment<wmma::matrix_b, 16, 16, 16, __half, wmma::col_major> bf[4];
#pragma unroll
            for (int mt = 0; mt < 4; mt++)
                wmma::load_matrix_sync(af[mt], As + (wm * 64 + mt * 16) * LDA + ks * 16, LDA);
#pragma unroll
            for (int nt = 0; nt < 4; nt++)
                wmma::load_matrix_sync(bf[nt], Bs + (wn * 64 + nt * 16) * LDA + ks * 16, LDA);
#pragma unroll
            for (int mt = 0; mt < 4; mt++)
#pragma unroll
                for (int nt = 0; nt < 4; nt++)
                    wmma::mma_sync(acc[mt][nt], af[mt], bf[nt], acc[mt][nt]);
        }
    }
    __syncthreads();   // tiles dead; reuse smem as fp32 stage

    // ---- stage accumulators to smem ----
    float* stage = (float*)(smem + OFF_STAGE);
#pragma unroll
    for (int mt = 0; mt < 4; mt++)
#pragma unroll
        for (int nt = 0; nt < 4; nt++)
            wmma::store_matrix_sync(stage + (wm * 64 + mt * 16) * STAGE_LD + wn * 64 + nt * 16,
                                    acc[mt][nt], STAGE_LD, wmma::mem_row_major);
    __syncthreads();

    // ---- epilogue: each of 8 warps owns 16 rows; lane owns 8 cols ----
    const float* sb_bias = (const float*)(smem + OFF_BIAS);
    const float* sb_g    = (const float*)(smem + OFF_GAMMA);
    const float* sb_b    = (const float*)(smem + OFF_BETA);
    const float* sb_lw   = (const float*)(smem + OFF_LW);
    const int c0 = lane * 8;

    float bia[8], gam[8], bet[8], lwv[8];
#pragma unroll
    for (int j = 0; j < 8; j++) {
        bia[j] = sb_bias[c0 + j];
        gam[j] = sb_g[c0 + j];
        bet[j] = sb_b[c0 + j];
        if (FINAL) lwv[j] = sb_lw[c0 + j];
    }
    const float lb0 = FINAL ? __ldg(lb) : 0.f;

#pragma unroll
    for (int i = 0; i < 16; i++) {
        const int row = wid * 16 + i;
        const int gr  = rowBase + row;
        float v[8];
        float s = 0.f;
#pragma unroll
        for (int j = 0; j < 8; j++) {
            v[j] = stage[row * STAGE_LD + c0 + j] + bia[j];
            s += v[j];
        }
        s = warp_sum(s);
        const float mean = s * (1.f / 256.f);
        float q = 0.f;
#pragma unroll
        for (int j = 0; j < 8; j++) {
            float d = v[j] - mean;
            q += d * d;
        }
        q = warp_sum(q);
        const float inv = rsqrtf(q * (1.f / 256.f) + 1e-5f);

        if (!FINAL) {
            __half2 hv[4];
#pragma unroll
            for (int j = 0; j < 4; j++) {
                float za = (v[2*j]   - mean) * inv * gam[2*j]   + bet[2*j];
                float zb = (v[2*j+1] - mean) * inv * gam[2*j+1] + bet[2*j+1];
                hv[j] = __floats2half2_rn(fmaxf(za, 0.f), fmaxf(zb, 0.f));
            }
            *(uint4*)(outh + (size_t)gr * FN + c0) = *(uint4*)hv;
        } else {
            float p = 0.f;
#pragma unroll
            for (int j = 0; j < 8; j++) {
                float z = (v[j] - mean) * inv * gam[j] + bet[j];
                p = fmaf(fmaxf(z, 0.f), lwv[j], p);
            }
            p = warp_sum(p);
            if (lane == 0) outf[gr] = p + lb0;
        }
    }
}

// ============================================================
// launch:
//   stream 0 : xconv -> wait(wconv) -> conv1 -> conv2 -> wait(gather)
//   stream A : wconv (weights, concurrent with xconv)
//   stream B : map -> gather (fully off critical path)
// ============================================================
extern "C" void kernel_launch(void* const* d_in, const int* in_sizes, int n_in,
                              void* d_out, int out_size) {
    const float* x   = (const float*)d_in[0];
    const float* w1  = (const float*)d_in[1];
    const float* b1  = (const float*)d_in[2];
    const float* g1  = (const float*)d_in[3];
    const float* be1 = (const float*)d_in[4];
    const float* w2  = (const float*)d_in[5];
    const float* b2  = (const float*)d_in[6];
    const float* g2  = (const float*)d_in[7];
    const float* be2 = (const float*)d_in[8];
    const float* lw  = (const float*)d_in[9];
    const float* lb  = (const float*)d_in[10];
    const int* target = (const int*)d_in[11];
    float* out = (float*)d_out;

    __half *xh, *h1h, *w1h, *w2h;
    cudaGetSymbolAddress((void**)&xh,  g_xh);
    cudaGetSymbolAddress((void**)&h1h, g_h1h);
    cudaGetSymbolAddress((void**)&w1h, g_w1h);
    cudaGetSymbolAddress((void**)&w2h, g_w2h);

    cudaFuncSetAttribute(conv_wmma_kernel<false>,
                         cudaFuncAttributeMaxDynamicSharedMemorySize, SMEM_BYTES);
    cudaFuncSetAttribute(conv_wmma_kernel<true>,
                         cudaFuncAttributeMaxDynamicSharedMemorySize, SMEM_BYTES);

    // lazy one-time stream/event creation (first call is the uncaptured
    // correctness call; captured calls only use them — GPU work identical)
    static cudaStream_t sA = nullptr, sB = nullptr;
    static cudaEvent_t  e_fork = nullptr, e_w = nullptr, e_g = nullptr;
    if (sA == nullptr) {
        cudaStreamCreateWithFlags(&sA, cudaStreamNonBlocking);
        cudaStreamCreateWithFlags(&sB, cudaStreamNonBlocking);
        cudaEventCreateWithFlags(&e_fork, cudaEventDisableTiming);
        cudaEventCreateWithFlags(&e_w,    cudaEventDisableTiming);
        cudaEventCreateWithFlags(&e_g,    cudaEventDisableTiming);
    }

    // fork point
    cudaEventRecord(e_fork, 0);
    cudaStreamWaitEvent(sA, e_fork, 0);
    cudaStreamWaitEvent(sB, e_fork, 0);

    // stream A: weight conversion (needed before conv1/conv2)
    wconv_kernel<<<KSUM * FN / 512, 512, 0, sA>>>(w1, w2);
    cudaEventRecord(e_w, sA);

    // stream B: map -> gather (independent of conv path; writes output 0)
    map_kernel<<<BSZ, TN, 0, sB>>>(target);
    gather_kernel<<<GROWS / 32, 256, 0, sB>>>(x, out);
    cudaEventRecord(e_g, sB);

    // stream 0: x conversion (MLP=8), then convs once weights are ready
    xconv_kernel<<<ROWS * DN / 4 / 4096, 512>>>(x);
    cudaStreamWaitEvent(0, e_w, 0);

    conv_wmma_kernel<false><<<ROWS / BM, NTHREADS, SMEM_BYTES>>>(
        xh, w1h, b1, g1, be1, nullptr, nullptr, h1h, nullptr);
    conv_wmma_kernel<true><<<ROWS / BM, NTHREADS, SMEM_BYTES>>>(
        h1h, w2h, b2, g2, be2, lw, lb, nullptr, out + OUT_LR_ELEMS);

    // join: output 0 not complete until gather finishes
    cudaStreamWaitEvent(0, e_g, 0);
}